// round 1
// baseline (speedup 1.0000x reference)
#include <cuda_runtime.h>
#include <math.h>

#define B_ 256
#define T_ 128
#define H_ 2048
#define C_ 10

// Ping-pong hidden state buffers (scratch via __device__ global: no allocs).
__device__ float g_h[2][B_ * H_];

__global__ void init_h_kernel() {
    int i = blockIdx.x * blockDim.x + threadIdx.x;
    if (i < B_ * H_) g_h[0][i] = 0.0f;
}

// One recurrence step: h_out = tanh(h_in @ W^T + x[:,t] * U + bh)
//   h_in : [B_, H_] row-major  (g_h[t&1])
//   W    : [H_, H_] row-major  (W[n][k])
//   C[m][n] = sum_k h_in[m][k] * W[n][k]
// CTA tile 64(M) x 64(N) x 16(K), 256 threads, 4x4 microtile.
#define BM 64
#define BN 64
#define BK 16

__global__ __launch_bounds__(256) void rnn_step_kernel(
    const float* __restrict__ x, const float* __restrict__ U,
    const float* __restrict__ W, const float* __restrict__ bh, int t)
{
    const float* __restrict__ h_in  = g_h[t & 1];
    float*       __restrict__ h_out = g_h[(t + 1) & 1];

    __shared__ __align__(16) float As[BK][BM];  // As[k][m]
    __shared__ __align__(16) float Bs[BK][BN];  // Bs[k][n]

    const int tid = threadIdx.x;
    const int tx = tid & 15;        // n group (0..15)
    const int ty = tid >> 4;        // m group (0..15)
    const int m0 = blockIdx.y * BM; // batch-row tile
    const int n0 = blockIdx.x * BN; // output-neuron tile

    // Loader mapping: 256 threads load 64 rows x 16 cols (as float4) per tile.
    const int lrow = tid >> 2;      // 0..63
    const int lq   = tid & 3;       // 0..3 -> k offset lq*4

    float acc[4][4] = {};

    const float* aptr = &h_in[(m0 + lrow) * H_ + lq * 4];
    const float* bptr = &W[(n0 + lrow) * H_ + lq * 4];

    for (int k0 = 0; k0 < H_; k0 += BK) {
        float4 av = *(const float4*)(aptr + k0);
        float4 bv = *(const float4*)(bptr + k0);
        __syncthreads();  // previous iter's smem reads done
        As[lq * 4 + 0][lrow] = av.x;
        As[lq * 4 + 1][lrow] = av.y;
        As[lq * 4 + 2][lrow] = av.z;
        As[lq * 4 + 3][lrow] = av.w;
        Bs[lq * 4 + 0][lrow] = bv.x;
        Bs[lq * 4 + 1][lrow] = bv.y;
        Bs[lq * 4 + 2][lrow] = bv.z;
        Bs[lq * 4 + 3][lrow] = bv.w;
        __syncthreads();

        #pragma unroll
        for (int k = 0; k < BK; k++) {
            float4 a4 = *(const float4*)&As[k][ty * 4];
            float4 b4 = *(const float4*)&Bs[k][tx * 4];
            float a[4] = {a4.x, a4.y, a4.z, a4.w};
            float b[4] = {b4.x, b4.y, b4.z, b4.w};
            #pragma unroll
            for (int i = 0; i < 4; i++)
                #pragma unroll
                for (int j = 0; j < 4; j++)
                    acc[i][j] = fmaf(a[i], b[j], acc[i][j]);
        }
    }

    // Epilogue: add rank-1 input term + bias, tanh, store.
    #pragma unroll
    for (int i = 0; i < 4; i++) {
        const int b = m0 + ty * 4 + i;
        const float xb = x[b * T_ + t];
        #pragma unroll
        for (int j = 0; j < 4; j++) {
            const int n = n0 + tx * 4 + j;
            float v = acc[i][j] + xb * U[n] + bh[n];
            h_out[b * H_ + n] = tanhf(v);
        }
    }
}

// Readout: out[b][c] = sum_k h_last[b][k] * V[c][k] + bp[c]; also copies
// h_last into the first B_*H_ elements of d_out.
__global__ __launch_bounds__(256) void final_kernel(
    const float* __restrict__ V, const float* __restrict__ bp,
    float* __restrict__ out)
{
    const int b = blockIdx.x;
    const int tid = threadIdx.x;
    const float* __restrict__ h = &g_h[0][b * H_];  // T_=128 even -> h_last in g_h[0]

    float acc[C_] = {};
    for (int k = tid; k < H_; k += 256) {
        float hv = h[k];
        out[b * H_ + k] = hv;  // h_last part of the output tuple
        #pragma unroll
        for (int c = 0; c < C_; c++)
            acc[c] = fmaf(hv, V[c * H_ + k], acc[c]);
    }

    __shared__ float red[256];
    float* outp = out + B_ * H_;
    for (int c = 0; c < C_; c++) {
        red[tid] = acc[c];
        __syncthreads();
        #pragma unroll
        for (int s = 128; s > 0; s >>= 1) {
            if (tid < s) red[tid] += red[tid + s];
            __syncthreads();
        }
        if (tid == 0) outp[b * C_ + c] = red[0] + bp[c];
        __syncthreads();
    }
}

extern "C" void kernel_launch(void* const* d_in, const int* in_sizes, int n_in,
                              void* d_out, int out_size) {
    // metadata order: x [B,T], U [H,1], W [H,H], V [C,H], bh [H], bp [C]
    const float* x  = (const float*)d_in[0];
    const float* U  = (const float*)d_in[1];
    const float* W  = (const float*)d_in[2];
    const float* V  = (const float*)d_in[3];
    const float* bh = (const float*)d_in[4];
    const float* bp = (const float*)d_in[5];
    float* out = (float*)d_out;

    init_h_kernel<<<(B_ * H_ + 255) / 256, 256>>>();

    dim3 grid(H_ / BN, B_ / BM);  // 32 x 4 = 128 CTAs
    for (int t = 0; t < T_; t++) {
        rnn_step_kernel<<<grid, 256>>>(x, U, W, bh, t);
    }

    final_kernel<<<B_, 256>>>(V, bp, out);
    (void)in_sizes; (void)n_in; (void)out_size;
}

// round 5
// speedup vs baseline: 2.7756x; 2.7756x over previous
#include <cuda_runtime.h>
#include <cuda_bf16.h>
#include <math.h>
#include <stdint.h>

#define B_ 256
#define T_ 128
#define H_ 2048
#define C_ 10

// ---------------- device globals (no allocs allowed) ----------------
__device__ __nv_bfloat16 g_hh[2][B_ * H_];   // h hi split, ping-pong
__device__ __nv_bfloat16 g_hl[2][B_ * H_];   // h lo split
__device__ __nv_bfloat16 g_Wh[H_ * H_];      // W hi split
__device__ __nv_bfloat16 g_Wl[H_ * H_];      // W lo split

// ---------------- helpers ----------------
__device__ __forceinline__ uint32_t smem_u32(const void* p) {
    uint32_t a;
    asm("{ .reg .u64 t; cvta.to.shared.u64 t, %1; cvt.u32.u64 %0, t; }"
        : "=r"(a) : "l"(p));
    return a;
}

__device__ __forceinline__ void cpa16(uint32_t dst, const void* src) {
    asm volatile("cp.async.cg.shared.global [%0], [%1], 16;"
                 :: "r"(dst), "l"(src));
}

#define LDSM4(r, addr)                                                         \
    asm volatile("ldmatrix.sync.aligned.m8n8.x4.shared.b16 {%0,%1,%2,%3}, [%4];"\
                 : "=r"((r)[0]), "=r"((r)[1]), "=r"((r)[2]), "=r"((r)[3])      \
                 : "r"(addr))

#define MMA16816(c, a, b0, b1)                                                 \
    asm volatile(                                                              \
        "mma.sync.aligned.m16n8k16.row.col.f32.bf16.bf16.f32 "                 \
        "{%0,%1,%2,%3}, {%4,%5,%6,%7}, {%8,%9}, {%0,%1,%2,%3};"                \
        : "+f"((c)[0]), "+f"((c)[1]), "+f"((c)[2]), "+f"((c)[3])               \
        : "r"((a)[0]), "r"((a)[1]), "r"((a)[2]), "r"((a)[3]),                  \
          "r"(b0), "r"(b1))

// ---------------- prep kernels ----------------
__global__ void init_h_kernel() {
    int i = blockIdx.x * blockDim.x + threadIdx.x;
    if (i < B_ * H_) {
        g_hh[0][i] = __float2bfloat16(0.0f);
        g_hl[0][i] = __float2bfloat16(0.0f);
    }
}

__global__ void wsplit_kernel(const float* __restrict__ W) {
    int i = blockIdx.x * blockDim.x + threadIdx.x;
    if (i < H_ * H_) {
        float w = W[i];
        __nv_bfloat16 hi = __float2bfloat16(w);
        g_Wh[i] = hi;
        g_Wl[i] = __float2bfloat16(w - __bfloat162float(hi));
    }
}

// ---------------- step kernel ----------------
// h' = tanh(h @ W^T + x_t * U + bh)
// CTA tile 64(M) x 64(N), K' = 3*2048 (split-bf16 3 products), BK=64,
// 8 warps (warp tile 32x16), 4-stage cp.async pipeline, mma.sync m16n8k16.
#define BM 64
#define BN 64
#define BK 64
#define STAGE_BYTES 16384    // A 8KB + B 8KB  (64 rows x 128B each)
#define NSTAGE 96            // 3 passes x 32 k-tiles

__device__ __forceinline__ void load_stage(int s, int tid, int m0, int n0,
                                           uint32_t smbase,
                                           const __nv_bfloat16* __restrict__ hh,
                                           const __nv_bfloat16* __restrict__ hl) {
    const int p = s >> 5;        // 0: Ah*Wh, 1: Ah*Wl, 2: Al*Wh
    const int sp = s & 31;
    const __nv_bfloat16* __restrict__ A  = (p < 2) ? hh : hl;
    const __nv_bfloat16* __restrict__ Bm = (p == 1) ? g_Wl : g_Wh;
    const int k0 = sp * BK;
    const uint32_t ab = smbase + (uint32_t)(s & 3) * STAGE_BYTES;
    const uint32_t bb = ab + 8192u;
#pragma unroll
    for (int j = 0; j < 2; j++) {
        const int q = tid + j * 256;       // 0..511
        const int r = q >> 3;              // row 0..63
        const int c = q & 7;               // 16B chunk 0..7
        const uint32_t off = (uint32_t)(r * 128) + (uint32_t)(((c ^ (r & 7)) << 4));
        cpa16(ab + off, A  + (size_t)(m0 + r) * H_ + k0 + c * 8);
        cpa16(bb + off, Bm + (size_t)(n0 + r) * H_ + k0 + c * 8);
    }
}

__global__ __launch_bounds__(256) void rnn_step_mma(
    const float* __restrict__ x, const float* __restrict__ U,
    const float* __restrict__ bh, int t)
{
    extern __shared__ __align__(16) char sm[];
    const uint32_t smbase = smem_u32(sm);

    const int tid = threadIdx.x;
    const int lane = tid & 31, wid = tid >> 5;
    const int wm = (wid >> 2) * 32;   // warp row base (0 / 32)
    const int wn = (wid & 3) * 16;    // warp col base (0..48)
    const int m0 = blockIdx.y * BM;
    const int n0 = blockIdx.x * BN;

    const __nv_bfloat16* __restrict__ hh = g_hh[t & 1];
    const __nv_bfloat16* __restrict__ hl = g_hl[t & 1];

    float acc[2][2][4] = {};

    // prologue: 3 stages in flight
#pragma unroll
    for (int s = 0; s < 3; s++) {
        load_stage(s, tid, m0, n0, smbase, hh, hl);
        asm volatile("cp.async.commit_group;" ::: "memory");
    }

    // per-lane ldmatrix address components
    const int aRow0 = wm + (lane & 15);                       // + mt*16
    const int aCsel = lane >> 4;                              // chunk +0/+1
    const int bRow  = wn + (lane & 7) + ((lane >> 4) << 3);   // n row
    const int bCsel = (lane >> 3) & 1;                        // chunk +0/+1

    for (int s = 0; s < NSTAGE; s++) {
        asm volatile("cp.async.wait_group 2;" ::: "memory");
        __syncthreads();
        if (s + 3 < NSTAGE)
            load_stage(s + 3, tid, m0, n0, smbase, hh, hl);
        asm volatile("cp.async.commit_group;" ::: "memory");

        const uint32_t ab = smbase + (uint32_t)(s & 3) * STAGE_BYTES;
        const uint32_t bb = ab + 8192u;
#pragma unroll
        for (int kk = 0; kk < 4; kk++) {
            uint32_t a[2][4], b[4];
#pragma unroll
            for (int mt = 0; mt < 2; mt++) {
                const int row = aRow0 + mt * 16;
                const uint32_t addr =
                    ab + (uint32_t)(row * 128) +
                    (uint32_t)((((kk * 2 + aCsel) ^ (row & 7)) << 4));
                LDSM4(a[mt], addr);
            }
            {
                const uint32_t addr =
                    bb + (uint32_t)(bRow * 128) +
                    (uint32_t)((((kk * 2 + bCsel) ^ (bRow & 7)) << 4));
                LDSM4(b, addr);
            }
#pragma unroll
            for (int mt = 0; mt < 2; mt++)
#pragma unroll
                for (int nt = 0; nt < 2; nt++)
                    MMA16816(acc[mt][nt], a[mt], b[nt * 2], b[nt * 2 + 1]);
        }
    }

    // ---------------- epilogue ----------------
    __nv_bfloat16* __restrict__ ghh = g_hh[(t + 1) & 1];
    __nv_bfloat16* __restrict__ ghl = g_hl[(t + 1) & 1];
    const int r4 = lane >> 2;
    const int c2 = (lane & 3) * 2;

#pragma unroll
    for (int mt = 0; mt < 2; mt++) {
#pragma unroll
        for (int rh = 0; rh < 2; rh++) {
            const int m = m0 + wm + mt * 16 + r4 + rh * 8;
            const float xb = x[m * T_ + t];
#pragma unroll
            for (int nt = 0; nt < 2; nt++) {
                const int n = n0 + wn + nt * 8 + c2;
                float v0 = acc[mt][nt][rh * 2 + 0] + xb * U[n]     + bh[n];
                float v1 = acc[mt][nt][rh * 2 + 1] + xb * U[n + 1] + bh[n + 1];
                float t0 = tanhf(v0), t1 = tanhf(v1);
                __nv_bfloat16 h0 = __float2bfloat16(t0);
                __nv_bfloat16 h1 = __float2bfloat16(t1);
                __nv_bfloat16 l0 = __float2bfloat16(t0 - __bfloat162float(h0));
                __nv_bfloat16 l1 = __float2bfloat16(t1 - __bfloat162float(h1));
                __nv_bfloat162 hp; hp.x = h0; hp.y = h1;
                __nv_bfloat162 lp; lp.x = l0; lp.y = l1;
                *(__nv_bfloat162*)(&ghh[(size_t)m * H_ + n]) = hp;
                *(__nv_bfloat162*)(&ghl[(size_t)m * H_ + n]) = lp;
            }
        }
    }
}

// ---------------- readout ----------------
__global__ __launch_bounds__(256) void final_kernel(
    const float* __restrict__ V, const float* __restrict__ bp,
    float* __restrict__ out)
{
    const int b = blockIdx.x;
    const int tid = threadIdx.x;
    const __nv_bfloat16* __restrict__ hi = &g_hh[0][b * H_];  // T_=128 even
    const __nv_bfloat16* __restrict__ lo = &g_hl[0][b * H_];

    float acc[C_] = {};
    for (int k = tid; k < H_; k += 256) {
        float hv = __bfloat162float(hi[k]) + __bfloat162float(lo[k]);
        out[b * H_ + k] = hv;
#pragma unroll
        for (int c = 0; c < C_; c++)
            acc[c] = fmaf(hv, V[c * H_ + k], acc[c]);
    }

    __shared__ float red[256];
    float* outp = out + B_ * H_;
    for (int c = 0; c < C_; c++) {
        red[tid] = acc[c];
        __syncthreads();
#pragma unroll
        for (int s = 128; s > 0; s >>= 1) {
            if (tid < s) red[tid] += red[tid + s];
            __syncthreads();
        }
        if (tid == 0) outp[b * C_ + c] = red[0] + bp[c];
        __syncthreads();
    }
}

// ---------------- launch ----------------
extern "C" void kernel_launch(void* const* d_in, const int* in_sizes, int n_in,
                              void* d_out, int out_size) {
    const float* x  = (const float*)d_in[0];
    const float* U  = (const float*)d_in[1];
    const float* W  = (const float*)d_in[2];
    const float* V  = (const float*)d_in[3];
    const float* bh = (const float*)d_in[4];
    const float* bp = (const float*)d_in[5];
    float* out = (float*)d_out;

    const int SMEM = 4 * STAGE_BYTES;  // 64 KB
    cudaFuncSetAttribute(rnn_step_mma, cudaFuncAttributeMaxDynamicSharedMemorySize, SMEM);

    init_h_kernel<<<(B_ * H_ + 255) / 256, 256>>>();
    wsplit_kernel<<<(H_ * H_ + 255) / 256, 256>>>(W);

    dim3 grid(H_ / BN, B_ / BM);  // 32 x 4 = 128 CTAs
    for (int t = 0; t < T_; t++) {
        rnn_step_mma<<<grid, 256, SMEM>>>(x, U, bh, t);
    }

    final_kernel<<<B_, 256>>>(V, bp, out);
    (void)in_sizes; (void)n_in; (void)out_size;
}

// round 8
// speedup vs baseline: 4.5076x; 1.6240x over previous
#include <cuda_runtime.h>
#include <cuda_bf16.h>
#include <math.h>
#include <stdint.h>

#define B_ 256
#define T_ 128
#define H_ 2048
#define C_ 10

// ---------------- device globals (no allocs allowed) ----------------
__device__ __nv_bfloat16 g_hh[2][B_ * H_];   // h hi split, ping-pong
__device__ __nv_bfloat16 g_hl[2][B_ * H_];   // h lo split
__device__ __nv_bfloat16 g_Wh[H_ * H_];      // W hi split
__device__ __nv_bfloat16 g_Wl[H_ * H_];      // W lo split

// ---------------- helpers ----------------
__device__ __forceinline__ uint32_t smem_u32(const void* p) {
    uint32_t a;
    asm("{ .reg .u64 t; cvta.to.shared.u64 t, %1; cvt.u32.u64 %0, t; }"
        : "=r"(a) : "l"(p));
    return a;
}

__device__ __forceinline__ void cpa16(uint32_t dst, const void* src) {
    asm volatile("cp.async.cg.shared.global [%0], [%1], 16;"
                 :: "r"(dst), "l"(src));
}

#define LDSM4(r, addr)                                                         \
    asm volatile("ldmatrix.sync.aligned.m8n8.x4.shared.b16 {%0,%1,%2,%3}, [%4];"\
                 : "=r"((r)[0]), "=r"((r)[1]), "=r"((r)[2]), "=r"((r)[3])      \
                 : "r"(addr))

#define MMA16816(c, a, b0, b1)                                                 \
    asm volatile(                                                              \
        "mma.sync.aligned.m16n8k16.row.col.f32.bf16.bf16.f32 "                 \
        "{%0,%1,%2,%3}, {%4,%5,%6,%7}, {%8,%9}, {%0,%1,%2,%3};"                \
        : "+f"((c)[0]), "+f"((c)[1]), "+f"((c)[2]), "+f"((c)[3])               \
        : "r"((a)[0]), "r"((a)[1]), "r"((a)[2]), "r"((a)[3]),                  \
          "r"(b0), "r"(b1))

// ---------------- prep kernels ----------------
__global__ void init_h_kernel() {
    int i = blockIdx.x * blockDim.x + threadIdx.x;
    if (i < B_ * H_) {
        g_hh[0][i] = __float2bfloat16(0.0f);
        g_hl[0][i] = __float2bfloat16(0.0f);
    }
}

__global__ void wsplit_kernel(const float* __restrict__ W) {
    int i = blockIdx.x * blockDim.x + threadIdx.x;
    if (i < H_ * H_) {
        float w = W[i];
        __nv_bfloat16 hi = __float2bfloat16(w);
        g_Wh[i] = hi;
        g_Wl[i] = __float2bfloat16(w - __bfloat162float(hi));
    }
}

// ---------------- step kernel ----------------
// h' = tanh(h @ W^T + x_t * U + bh)
// CTA tile 64(M) x 64(N), fused split-bf16: per k-tile (BK=64) load
// Ah, Al, Wh, Wl once and issue 3 products (AhWh -> acch; AhWl, AlWh -> accl).
// 8 warps (warp tile 32x16), 4-deep cp.async pipeline (32KB/stage).
#define BM 64
#define BN 64
#define BK 64
#define STAGE_BYTES 32768    // Ah 8K | Al 8K | Wh 8K | Wl 8K (64 rows x 128B each)
#define NSTAGE 32            // 2048 / 64

__device__ __forceinline__ void load_stage(int s, int tid, int m0, int n0,
                                           uint32_t smbase,
                                           const __nv_bfloat16* __restrict__ hh,
                                           const __nv_bfloat16* __restrict__ hl) {
    const int k0 = s * BK;
    const uint32_t sb = smbase + (uint32_t)(s & 3) * STAGE_BYTES;
#pragma unroll
    for (int j = 0; j < 8; j++) {
        const int q = tid + ((j & 1) << 8);     // 0..511 within matrix
        const int r = q >> 3;                   // row 0..63
        const int c = q & 7;                    // 16B chunk 0..7
        const uint32_t off = (uint32_t)(r * 128) + (uint32_t)(((c ^ (r & 7)) << 4));
        const uint32_t dst = sb + (uint32_t)(j >> 1) * 8192u + off;
        const __nv_bfloat16* src;
        if ((j >> 1) == 0)      src = hh   + (size_t)(m0 + r) * H_ + k0 + c * 8;
        else if ((j >> 1) == 1) src = hl   + (size_t)(m0 + r) * H_ + k0 + c * 8;
        else if ((j >> 1) == 2) src = g_Wh + (size_t)(n0 + r) * H_ + k0 + c * 8;
        else                    src = g_Wl + (size_t)(n0 + r) * H_ + k0 + c * 8;
        cpa16(dst, src);
    }
}

__global__ __launch_bounds__(256, 1) void rnn_step_mma(
    const float* __restrict__ x, const float* __restrict__ U,
    const float* __restrict__ bh, int t)
{
    extern __shared__ __align__(16) char sm[];
    const uint32_t smbase = smem_u32(sm);

    const int tid = threadIdx.x;
    const int lane = tid & 31, wid = tid >> 5;
    const int wm = (wid >> 2) * 32;   // warp row base (0 / 32)
    const int wn = (wid & 3) * 16;    // warp col base (0..48)
    const int m0 = blockIdx.y * BM;
    const int n0 = blockIdx.x * BN;

    const __nv_bfloat16* __restrict__ hh = g_hh[t & 1];
    const __nv_bfloat16* __restrict__ hl = g_hl[t & 1];

    float acch[2][2][4] = {};   // Ah*Wh
    float accl[2][2][4] = {};   // Ah*Wl + Al*Wh

    // prologue: 3 stages in flight
#pragma unroll
    for (int s = 0; s < 3; s++) {
        load_stage(s, tid, m0, n0, smbase, hh, hl);
        asm volatile("cp.async.commit_group;" ::: "memory");
    }

    // per-lane ldmatrix address components
    const int aRow0 = wm + (lane & 15);                       // + mt*16
    const int aCsel = lane >> 4;                              // chunk +0/+1
    const int bRow  = wn + (lane & 7) + ((lane >> 4) << 3);   // n row
    const int bCsel = (lane >> 3) & 1;                        // chunk +0/+1

    for (int s = 0; s < NSTAGE; s++) {
        asm volatile("cp.async.wait_group 2;" ::: "memory");
        __syncthreads();
        if (s + 3 < NSTAGE)
            load_stage(s + 3, tid, m0, n0, smbase, hh, hl);
        asm volatile("cp.async.commit_group;" ::: "memory");

        const uint32_t sb = smbase + (uint32_t)(s & 3) * STAGE_BYTES;
#pragma unroll
        for (int kk = 0; kk < 4; kk++) {
            uint32_t ah[2][4], al[2][4], wh[4], wl[4];
#pragma unroll
            for (int mt = 0; mt < 2; mt++) {
                const int row = aRow0 + mt * 16;
                const uint32_t ro = (uint32_t)(row * 128) +
                    (uint32_t)((((kk * 2 + aCsel) ^ (row & 7)) << 4));
                LDSM4(ah[mt], sb + ro);
                LDSM4(al[mt], sb + 8192u + ro);
            }
            {
                const uint32_t ro = (uint32_t)(bRow * 128) +
                    (uint32_t)((((kk * 2 + bCsel) ^ (bRow & 7)) << 4));
                LDSM4(wh, sb + 16384u + ro);
                LDSM4(wl, sb + 24576u + ro);
            }
#pragma unroll
            for (int mt = 0; mt < 2; mt++)
#pragma unroll
                for (int nt = 0; nt < 2; nt++) {
                    MMA16816(acch[mt][nt], ah[mt], wh[nt * 2], wh[nt * 2 + 1]);
                    MMA16816(accl[mt][nt], ah[mt], wl[nt * 2], wl[nt * 2 + 1]);
                    MMA16816(accl[mt][nt], al[mt], wh[nt * 2], wh[nt * 2 + 1]);
                }
        }
    }

    // ---------------- epilogue ----------------
    __nv_bfloat16* __restrict__ ghh = g_hh[(t + 1) & 1];
    __nv_bfloat16* __restrict__ ghl = g_hl[(t + 1) & 1];
    const int r4 = lane >> 2;
    const int c2 = (lane & 3) * 2;

#pragma unroll
    for (int mt = 0; mt < 2; mt++) {
#pragma unroll
        for (int rh = 0; rh < 2; rh++) {
            const int m = m0 + wm + mt * 16 + r4 + rh * 8;
            const float xb = x[m * T_ + t];
#pragma unroll
            for (int nt = 0; nt < 2; nt++) {
                const int n = n0 + wn + nt * 8 + c2;
                float v0 = acch[mt][nt][rh * 2 + 0] + accl[mt][nt][rh * 2 + 0]
                           + xb * U[n]     + bh[n];
                float v1 = acch[mt][nt][rh * 2 + 1] + accl[mt][nt][rh * 2 + 1]
                           + xb * U[n + 1] + bh[n + 1];
                float t0 = tanhf(v0), t1 = tanhf(v1);
                __nv_bfloat16 h0 = __float2bfloat16(t0);
                __nv_bfloat16 h1 = __float2bfloat16(t1);
                __nv_bfloat16 l0 = __float2bfloat16(t0 - __bfloat162float(h0));
                __nv_bfloat16 l1 = __float2bfloat16(t1 - __bfloat162float(h1));
                __nv_bfloat162 hp; hp.x = h0; hp.y = h1;
                __nv_bfloat162 lp; lp.x = l0; lp.y = l1;
                *(__nv_bfloat162*)(&ghh[(size_t)m * H_ + n]) = hp;
                *(__nv_bfloat162*)(&ghl[(size_t)m * H_ + n]) = lp;
            }
        }
    }
}

// ---------------- readout ----------------
__global__ __launch_bounds__(256) void final_kernel(
    const float* __restrict__ V, const float* __restrict__ bp,
    float* __restrict__ out)
{
    const int b = blockIdx.x;
    const int tid = threadIdx.x;
    const __nv_bfloat16* __restrict__ hi = &g_hh[0][b * H_];  // T_=128 even
    const __nv_bfloat16* __restrict__ lo = &g_hl[0][b * H_];

    float acc[C_] = {};
    for (int k = tid; k < H_; k += 256) {
        float hv = __bfloat162float(hi[k]) + __bfloat162float(lo[k]);
        out[b * H_ + k] = hv;
#pragma unroll
        for (int c = 0; c < C_; c++)
            acc[c] = fmaf(hv, V[c * H_ + k], acc[c]);
    }

    __shared__ float red[256];
    float* outp = out + B_ * H_;
    for (int c = 0; c < C_; c++) {
        red[tid] = acc[c];
        __syncthreads();
#pragma unroll
        for (int s = 128; s > 0; s >>= 1) {
            if (tid < s) red[tid] += red[tid + s];
            __syncthreads();
        }
        if (tid == 0) outp[b * C_ + c] = red[0] + bp[c];
        __syncthreads();
    }
}

// ---------------- launch ----------------
extern "C" void kernel_launch(void* const* d_in, const int* in_sizes, int n_in,
                              void* d_out, int out_size) {
    const float* x  = (const float*)d_in[0];
    const float* U  = (const float*)d_in[1];
    const float* W  = (const float*)d_in[2];
    const float* V  = (const float*)d_in[3];
    const float* bh = (const float*)d_in[4];
    const float* bp = (const float*)d_in[5];
    float* out = (float*)d_out;

    const int SMEM = 4 * STAGE_BYTES;  // 128 KB
    cudaFuncSetAttribute(rnn_step_mma, cudaFuncAttributeMaxDynamicSharedMemorySize, SMEM);

    init_h_kernel<<<(B_ * H_ + 255) / 256, 256>>>();
    wsplit_kernel<<<(H_ * H_ + 255) / 256, 256>>>(W);

    dim3 grid(H_ / BN, B_ / BM);  // 32 x 4 = 128 CTAs
    for (int t = 0; t < T_; t++) {
        rnn_step_mma<<<grid, 256, SMEM>>>(x, U, bh, t);
    }

    final_kernel<<<B_, 256>>>(V, bp, out);
    (void)in_sizes; (void)n_in; (void)out_size;
}

// round 9
// speedup vs baseline: 4.7661x; 1.0573x over previous
#include <cuda_runtime.h>
#include <cuda_bf16.h>
#include <math.h>
#include <stdint.h>

#define B_ 256
#define T_ 128
#define H_ 2048
#define C_ 10

// ---------------- device globals (no allocs allowed) ----------------
__device__ __nv_bfloat16 g_hh[2][B_ * H_];   // h hi split, ping-pong
__device__ __nv_bfloat16 g_hl[2][B_ * H_];   // h lo split
__device__ __nv_bfloat16 g_Wh[H_ * H_];      // W hi split
__device__ __nv_bfloat16 g_Wl[H_ * H_];      // W lo split

// ---------------- helpers ----------------
__device__ __forceinline__ uint32_t smem_u32(const void* p) {
    uint32_t a;
    asm("{ .reg .u64 t; cvta.to.shared.u64 t, %1; cvt.u32.u64 %0, t; }"
        : "=r"(a) : "l"(p));
    return a;
}

__device__ __forceinline__ void cpa16(uint32_t dst, const void* src) {
    asm volatile("cp.async.cg.shared.global [%0], [%1], 16;"
                 :: "r"(dst), "l"(src));
}

#define LDSM4(r, addr)                                                         \
    asm volatile("ldmatrix.sync.aligned.m8n8.x4.shared.b16 {%0,%1,%2,%3}, [%4];"\
                 : "=r"((r)[0]), "=r"((r)[1]), "=r"((r)[2]), "=r"((r)[3])      \
                 : "r"(addr))

#define MMA16816(c, a, b0, b1)                                                 \
    asm volatile(                                                              \
        "mma.sync.aligned.m16n8k16.row.col.f32.bf16.bf16.f32 "                 \
        "{%0,%1,%2,%3}, {%4,%5,%6,%7}, {%8,%9}, {%0,%1,%2,%3};"                \
        : "+f"((c)[0]), "+f"((c)[1]), "+f"((c)[2]), "+f"((c)[3])               \
        : "r"((a)[0]), "r"((a)[1]), "r"((a)[2]), "r"((a)[3]),                  \
          "r"(b0), "r"(b1))

// ---------------- prep kernels ----------------
__global__ void init_h_kernel() {
    int i = blockIdx.x * blockDim.x + threadIdx.x;
    if (i < B_ * H_) {
        g_hh[0][i] = __float2bfloat16(0.0f);
        g_hl[0][i] = __float2bfloat16(0.0f);
    }
}

__global__ void wsplit_kernel(const float* __restrict__ W) {
    int i = blockIdx.x * blockDim.x + threadIdx.x;
    if (i < H_ * H_) {
        float w = W[i];
        __nv_bfloat16 hi = __float2bfloat16(w);
        g_Wh[i] = hi;
        g_Wl[i] = __float2bfloat16(w - __bfloat162float(hi));
    }
}

// ---------------- step kernel ----------------
// h' = tanh(h @ W^T + x_t * U + bh)
// CTA tile 64x64, BK=128, 16 stages, 3-deep cp.async pipeline (64KB/stage).
// 8 warps: 2 K-groups x 4 spatial warps, warp tile 32x32 (3 fused split-bf16
// products per k16). Cross-group fp32 reduce + epilogue through smem.
#define BM 64
#define BN 64
#define BK 128
#define TILE_B 16384         // one 64x256B operand tile
#define STAGE_BYTES 65536    // Ah | Al | Wh | Wl
#define NSTAGE 16            // 2048 / 128

// swizzled chunk index within a 256B row (16 chunks of 16B)
__device__ __forceinline__ uint32_t swz(int chunk, int row) {
    return (uint32_t)((chunk & 8) | ((chunk ^ (row & 7)) & 7));
}

__device__ __forceinline__ void load_stage(int s, int tid, int m0, int n0,
                                           uint32_t smbase,
                                           const __nv_bfloat16* __restrict__ hh,
                                           const __nv_bfloat16* __restrict__ hl) {
    const int k0 = s * BK;
    const uint32_t sb = smbase + (uint32_t)(s % 3) * STAGE_BYTES;
#pragma unroll
    for (int j = 0; j < 16; j++) {
        const int tile = j >> 2;            // 0 Ah, 1 Al, 2 Wh, 3 Wl
        const int q = tid + ((j & 3) << 8); // 0..1023 chunk in tile
        const int r = q >> 4;               // row 0..63
        const int c = q & 15;               // 16B chunk 0..15
        const uint32_t dst = sb + (uint32_t)tile * TILE_B +
                             (uint32_t)(r * 256) + swz(c, r) * 16u;
        const __nv_bfloat16* src;
        if (tile == 0)      src = hh   + (size_t)(m0 + r) * H_ + k0 + c * 8;
        else if (tile == 1) src = hl   + (size_t)(m0 + r) * H_ + k0 + c * 8;
        else if (tile == 2) src = g_Wh + (size_t)(n0 + r) * H_ + k0 + c * 8;
        else                src = g_Wl + (size_t)(n0 + r) * H_ + k0 + c * 8;
        cpa16(dst, src);
    }
}

__global__ __launch_bounds__(256, 1) void rnn_step_mma(
    const float* __restrict__ x, const float* __restrict__ U,
    const float* __restrict__ bh, int t)
{
    extern __shared__ __align__(16) char sm[];
    const uint32_t smbase = smem_u32(sm);

    const int tid = threadIdx.x;
    const int lane = tid & 31, wid = tid >> 5;
    const int g  = wid >> 2;          // K-group 0/1
    const int w2 = wid & 3;
    const int wm = (w2 >> 1) * 32;    // warp row base 0/32
    const int wn = (w2 & 1) * 32;     // warp col base 0/32
    const int m0 = blockIdx.y * BM;
    const int n0 = blockIdx.x * BN;

    const __nv_bfloat16* __restrict__ hh = g_hh[t & 1];
    const __nv_bfloat16* __restrict__ hl = g_hl[t & 1];

    float acch[2][4][4] = {};   // Ah*Wh
    float accl[2][4][4] = {};   // Ah*Wl + Al*Wh

    // prologue: 2 stages in flight
#pragma unroll
    for (int s = 0; s < 2; s++) {
        load_stage(s, tid, m0, n0, smbase, hh, hl);
        asm volatile("cp.async.commit_group;" ::: "memory");
    }

    const int aRow0 = wm + (lane & 15);
    const int aCsel = lane >> 4;
    const int bRow0 = wn + (lane & 7) + ((lane >> 4) << 3);
    const int bCsel = (lane >> 3) & 1;

    for (int s = 0; s < NSTAGE; s++) {
        asm volatile("cp.async.wait_group 1;" ::: "memory");
        __syncthreads();
        if (s + 2 < NSTAGE) {
            load_stage(s + 2, tid, m0, n0, smbase, hh, hl);
            asm volatile("cp.async.commit_group;" ::: "memory");
        }

        const uint32_t sb = smbase + (uint32_t)(s % 3) * STAGE_BYTES;
#pragma unroll
        for (int kq = 0; kq < 4; kq++) {
            const int kk = g * 4 + kq;   // this group's k16 index in stage
            uint32_t ah[2][4], al[2][4], wh[2][4], wl[2][4];
#pragma unroll
            for (int mt = 0; mt < 2; mt++) {
                const int row = aRow0 + mt * 16;
                const uint32_t ro = (uint32_t)(row * 256) +
                                    swz(kk * 2 + aCsel, row) * 16u;
                LDSM4(ah[mt], sb + ro);
                LDSM4(al[mt], sb + TILE_B + ro);
            }
#pragma unroll
            for (int bt = 0; bt < 2; bt++) {
                const int row = bRow0 + bt * 16;
                const uint32_t ro = (uint32_t)(row * 256) +
                                    swz(kk * 2 + bCsel, row) * 16u;
                LDSM4(wh[bt], sb + 2 * TILE_B + ro);
                LDSM4(wl[bt], sb + 3 * TILE_B + ro);
            }
#pragma unroll
            for (int mt = 0; mt < 2; mt++)
#pragma unroll
                for (int nt = 0; nt < 4; nt++) {
                    const int bt = nt >> 1, pi = (nt & 1) * 2;
                    MMA16816(acch[mt][nt], ah[mt], wh[bt][pi], wh[bt][pi + 1]);
                    MMA16816(accl[mt][nt], ah[mt], wl[bt][pi], wl[bt][pi + 1]);
                    MMA16816(accl[mt][nt], al[mt], wh[bt][pi], wh[bt][pi + 1]);
                }
        }
    }

    // ---------------- cross-group reduce + epilogue (via smem) ----------------
    __syncthreads();   // all LDSM reads of last stage done before overwrite

    float* P = (float*)sm;            // two partials: [g][64][65]
    const int go = g * (64 * 65);
    const int r4 = lane >> 2;
    const int c2 = (lane & 3) * 2;
#pragma unroll
    for (int mt = 0; mt < 2; mt++)
#pragma unroll
        for (int nt = 0; nt < 4; nt++)
#pragma unroll
            for (int rh = 0; rh < 2; rh++) {
                const int row = wm + mt * 16 + r4 + rh * 8;
                const int col = wn + nt * 8 + c2;
                P[go + row * 65 + col]     = acch[mt][nt][rh * 2 + 0] + accl[mt][nt][rh * 2 + 0];
                P[go + row * 65 + col + 1] = acch[mt][nt][rh * 2 + 1] + accl[mt][nt][rh * 2 + 1];
            }
    __syncthreads();

    __nv_bfloat16* __restrict__ ghh = g_hh[(t + 1) & 1];
    __nv_bfloat16* __restrict__ ghl = g_hl[(t + 1) & 1];
#pragma unroll
    for (int q = 0; q < 8; q++) {
        const int e = tid + q * 256;       // 0..2047 (pair index)
        const int row = e >> 5;
        const int col = (e & 31) * 2;
        const int m = m0 + row, n = n0 + col;
        const float xb = x[m * T_ + t];
        float v0 = P[row * 65 + col]     + P[64 * 65 + row * 65 + col]
                   + xb * U[n]     + bh[n];
        float v1 = P[row * 65 + col + 1] + P[64 * 65 + row * 65 + col + 1]
                   + xb * U[n + 1] + bh[n + 1];
        float t0 = tanhf(v0), t1 = tanhf(v1);
        __nv_bfloat16 h0 = __float2bfloat16(t0);
        __nv_bfloat16 h1 = __float2bfloat16(t1);
        __nv_bfloat16 l0 = __float2bfloat16(t0 - __bfloat162float(h0));
        __nv_bfloat16 l1 = __float2bfloat16(t1 - __bfloat162float(h1));
        __nv_bfloat162 hp; hp.x = h0; hp.y = h1;
        __nv_bfloat162 lp; lp.x = l0; lp.y = l1;
        *(__nv_bfloat162*)(&ghh[(size_t)m * H_ + n]) = hp;
        *(__nv_bfloat162*)(&ghl[(size_t)m * H_ + n]) = lp;
    }
}

// ---------------- readout ----------------
__global__ __launch_bounds__(256) void final_kernel(
    const float* __restrict__ V, const float* __restrict__ bp,
    float* __restrict__ out)
{
    const int b = blockIdx.x;
    const int tid = threadIdx.x;
    const __nv_bfloat16* __restrict__ hi = &g_hh[0][b * H_];  // T_=128 even
    const __nv_bfloat16* __restrict__ lo = &g_hl[0][b * H_];

    float acc[C_] = {};
    for (int k = tid; k < H_; k += 256) {
        float hv = __bfloat162float(hi[k]) + __bfloat162float(lo[k]);
        out[b * H_ + k] = hv;
#pragma unroll
        for (int c = 0; c < C_; c++)
            acc[c] = fmaf(hv, V[c * H_ + k], acc[c]);
    }

    __shared__ float red[256];
    float* outp = out + B_ * H_;
    for (int c = 0; c < C_; c++) {
        red[tid] = acc[c];
        __syncthreads();
#pragma unroll
        for (int s = 128; s > 0; s >>= 1) {
            if (tid < s) red[tid] += red[tid + s];
            __syncthreads();
        }
        if (tid == 0) outp[b * C_ + c] = red[0] + bp[c];
        __syncthreads();
    }
}

// ---------------- launch ----------------
extern "C" void kernel_launch(void* const* d_in, const int* in_sizes, int n_in,
                              void* d_out, int out_size) {
    const float* x  = (const float*)d_in[0];
    const float* U  = (const float*)d_in[1];
    const float* W  = (const float*)d_in[2];
    const float* V  = (const float*)d_in[3];
    const float* bh = (const float*)d_in[4];
    const float* bp = (const float*)d_in[5];
    float* out = (float*)d_out;

    const int SMEM = 3 * STAGE_BYTES;  // 192 KB
    cudaFuncSetAttribute(rnn_step_mma, cudaFuncAttributeMaxDynamicSharedMemorySize, SMEM);

    init_h_kernel<<<(B_ * H_ + 255) / 256, 256>>>();
    wsplit_kernel<<<(H_ * H_ + 255) / 256, 256>>>(W);

    dim3 grid(H_ / BN, B_ / BM);  // 32 x 4 = 128 CTAs
    for (int t = 0; t < T_; t++) {
        rnn_step_mma<<<grid, 256, SMEM>>>(x, U, bh, t);
    }

    final_kernel<<<B_, 256>>>(V, bp, out);
    (void)in_sizes; (void)n_in; (void)out_size;
}